// round 15
// baseline (speedup 1.0000x reference)
#include <cuda_runtime.h>
#include <cuda_fp16.h>
#include <cstdint>

// ---------------- problem constants ----------------
static constexpr int B_ROWS = 65536;
static constexpr int D_DIM  = 512;   // K
static constexpr int O_DIM  = 512;   // N
static constexpr int GRID_G = 16;

// ---------------- scratch (no allocs allowed) ----------------
__device__ __half g_A_h[(size_t)B_ROWS * D_DIM];
__device__ __half g_M_h[(size_t)O_DIM * D_DIM];
__device__ float2 g_tab[D_DIM * GRID_G];     // (base, slope) packed

// ---------------- kernel 0: mix->fp16 + table pack (fused) ---------------
__global__ void __launch_bounds__(256) prep_kernel(
    const float* __restrict__ mix,
    const float* __restrict__ bases,
    const float* __restrict__ slopes)
{
    if (blockIdx.x < 256) {
        size_t i4 = (size_t)blockIdx.x * 256 + threadIdx.x;   // 65536 float4s
        float4 mv = reinterpret_cast<const float4*>(mix)[i4];
        union { __half h[4]; uint2 v; } o;
        o.h[0] = __float2half_rn(mv.x);
        o.h[1] = __float2half_rn(mv.y);
        o.h[2] = __float2half_rn(mv.z);
        o.h[3] = __float2half_rn(mv.w);
        reinterpret_cast<uint2*>(g_M_h)[i4] = o.v;
    } else {
        int i = (blockIdx.x - 256) * 256 + threadIdx.x;       // 0..8191
        g_tab[i] = make_float2(bases[i], slopes[i]);
    }
}

// ---------------- kernel 1: spline -> fp16 (round-3 form, 2 float4/thread) ----
__global__ void __launch_bounds__(256) spline_kernel(const float* __restrict__ x)
{
    const float NORM_MAX = 1.0f - 1e-6f;
    size_t base4 = (size_t)blockIdx.x * 512 + threadIdx.x;   // 2 float4s per thread

    float4 xv0 = __ldg(reinterpret_cast<const float4*>(x) + base4);
    float4 xv1 = __ldg(reinterpret_cast<const float4*>(x) + base4 + 256);

    float xsv[2][4] = {{xv0.x, xv0.y, xv0.z, xv0.w}, {xv1.x, xv1.y, xv1.z, xv1.w}};
    union { __half h[4]; uint2 v; } o[2];

#pragma unroll
    for (int p = 0; p < 2; p++) {
        size_t i4 = base4 + p * 256;
        int d0 = (int)((i4 * 4) & (D_DIM - 1));
#pragma unroll
        for (int j = 0; j < 4; j++) {
            // bit-exact op order vs reference: (x+1)*0.5 (== /2), clip, *16 (exact), trunc
            float xn = (xsv[p][j] + 1.0f) * 0.5f;
            xn = fminf(fmaxf(xn, 0.0f), NORM_MAX);
            float t = xn * 16.0f;
            int idx = (int)t;
            idx = idx < 0 ? 0 : (idx > GRID_G - 1 ? GRID_G - 1 : idx);
            float xl = t - (float)idx;
            float2 bs = __ldg(&g_tab[(d0 + j) * GRID_G + idx]);
            o[p].h[j] = __float2half_rn(bs.x + bs.y * xl);
        }
    }
    reinterpret_cast<uint2*>(g_A_h)[base4]       = o[0].v;
    reinterpret_cast<uint2*>(g_A_h)[base4 + 256] = o[1].v;
}

// ---------------- GEMM: persistent, 4 warps, warp tile 64x64 (R11 proven) -------
static constexpr int BM = 128;
static constexpr int BN = 128;
static constexpr int BK = 64;
static constexpr int NSTAGE = 3;
static constexpr int KI = D_DIM / BK;                    // 8 k-iters per tile
static constexpr int STAGE_BYTES = (BM + BN) * BK * 2;   // 32 KB
static constexpr int SMEM_BYTES = NSTAGE * STAGE_BYTES;  // 96 KB
static constexpr int N_TILES = (B_ROWS / BM) * (O_DIM / BN);   // 2048
static constexpr int GRID_CTAS = 296;    // exactly 2 CTA/SM x 148 SMs; mult of 4
static constexpr int GT = 128;           // GEMM threads

__device__ __forceinline__ uint32_t smem_u32(const void* p) {
    uint32_t a;
    asm("{ .reg .u64 t; cvta.to.shared.u64 t, %1; cvt.u32.u64 %0, t; }" : "=r"(a) : "l"(p));
    return a;
}
__device__ __forceinline__ void cp_async16(uint32_t dst, const void* src) {
    asm volatile("cp.async.cg.shared.global [%0], [%1], 16;" :: "r"(dst), "l"(src));
}
#define CP_COMMIT() asm volatile("cp.async.commit_group;" ::: "memory")
template<int N>
__device__ __forceinline__ void cp_wait() {
    asm volatile("cp.async.wait_group %0;" :: "n"(N) : "memory");
}
__device__ __forceinline__ void ldsm_x4(uint32_t (&r)[4], uint32_t addr) {
    asm volatile("ldmatrix.sync.aligned.m8n8.x4.shared.b16 {%0,%1,%2,%3}, [%4];"
                 : "=r"(r[0]), "=r"(r[1]), "=r"(r[2]), "=r"(r[3]) : "r"(addr));
}
__device__ __forceinline__ void mma_16816(float (&c)[4], const uint32_t (&a)[4],
                                          uint32_t b0, uint32_t b1) {
    asm volatile(
        "mma.sync.aligned.m16n8k16.row.col.f32.f16.f16.f32 "
        "{%0,%1,%2,%3}, {%4,%5,%6,%7}, {%8,%9}, {%0,%1,%2,%3};"
        : "+f"(c[0]), "+f"(c[1]), "+f"(c[2]), "+f"(c[3])
        : "r"(a[0]), "r"(a[1]), "r"(a[2]), "r"(a[3]), "r"(b0), "r"(b1));
}
__device__ __forceinline__ uint32_t tile_addr(uint32_t base, int row, int kchunk) {
    return base + row * 128 + (((uint32_t)kchunk ^ ((uint32_t)row & 7)) << 4);
}

__global__ void __launch_bounds__(GT, 2) kan_gemm_kernel(
    const float* __restrict__ bias, float* __restrict__ out)
{
    extern __shared__ uint8_t smem[];
    const int tid  = threadIdx.x;
    const int wid  = tid >> 5;
    const int lane = tid & 31;
    const int wm = (wid & 1) * 64;           // 2 warps in M
    const int wn = (wid >> 1) * 64;          // 2 warps in N

    const int cta = blockIdx.x;
    const int n_base = (cta & 3) * BN;       // fixed for this CTA

    const uint32_t smem_base = smem_u32(smem);
    uint32_t sA[NSTAGE], sB[NSTAGE];
#pragma unroll
    for (int s = 0; s < NSTAGE; s++) {
        sA[s] = smem_base + s * STAGE_BYTES;
        sB[s] = sA[s] + BM * BK * 2;
    }

    auto load_stage = [&](int stage, int lt, int lk) {
        const int m_b  = (lt >> 2) * BM;
        const int koff = lk * BK;
#pragma unroll
        for (int j = 0; j < 8; j++) {
            int ch  = tid + j * GT;          // 0..1023
            int row = ch >> 3, c = ch & 7;
            cp_async16(tile_addr(sA[stage], row, c),
                       g_A_h + (size_t)(m_b + row) * D_DIM + koff + c * 8);
        }
#pragma unroll
        for (int j = 0; j < 8; j++) {
            int ch  = tid + j * GT;
            int row = ch >> 3, c = ch & 7;
            cp_async16(tile_addr(sB[stage], row, c),
                       g_M_h + (size_t)(n_base + row) * D_DIM + koff + c * 8);
        }
    };

    float bias_v[8][2];
    {
        const int tg = lane & 3;
#pragma unroll
        for (int nf = 0; nf < 8; nf++) {
            int n = n_base + wn + nf * 8 + tg * 2;
            bias_v[nf][0] = __ldg(bias + n);
            bias_v[nf][1] = __ldg(bias + n + 1);
        }
    }

    int lt = cta, lk = 0;
    load_stage(0, lt, lk); CP_COMMIT();
    if (++lk == KI) { lk = 0; lt += GRID_CTAS; }
    load_stage(1, lt, lk); CP_COMMIT();
    if (++lk == KI) { lk = 0; lt += GRID_CTAS; }

    int cs = 0;
    for (int t = cta; t < N_TILES; t += GRID_CTAS) {
        float acc[4][8][4];
#pragma unroll
        for (int i = 0; i < 4; i++)
#pragma unroll
            for (int j = 0; j < 8; j++)
#pragma unroll
                for (int k = 0; k < 4; k++) acc[i][j][k] = 0.0f;

        for (int it = 0; it < KI; it++) {
            cp_wait<1>();
            __syncthreads();

            const uint32_t a_base = sA[cs];
            const uint32_t b_base = sB[cs];

#pragma unroll
            for (int s = 0; s < BK / 16; s++) {
                uint32_t afr[4][4];
#pragma unroll
                for (int mf = 0; mf < 4; mf++) {
                    int row = wm + mf * 16 + (lane & 15);
                    int kc  = 2 * s + (lane >> 4);
                    ldsm_x4(afr[mf], tile_addr(a_base, row, kc));
                }
                uint32_t bfr[8][2];
#pragma unroll
                for (int h = 0; h < 4; h++) {
                    int row = wn + h * 16 + (lane & 7) + ((lane >> 4) << 3);
                    int kc  = 2 * s + ((lane >> 3) & 1);
                    uint32_t r[4];
                    ldsm_x4(r, tile_addr(b_base, row, kc));
                    bfr[h * 2 + 0][0] = r[0]; bfr[h * 2 + 0][1] = r[1];
                    bfr[h * 2 + 1][0] = r[2]; bfr[h * 2 + 1][1] = r[3];
                }
#pragma unroll
                for (int mf = 0; mf < 4; mf++)
#pragma unroll
                    for (int nf = 0; nf < 8; nf++)
                        mma_16816(acc[mf][nf], afr[mf], bfr[nf][0], bfr[nf][1]);
            }

            int ls = cs + 2; if (ls >= NSTAGE) ls -= NSTAGE;
            if (lt < N_TILES) load_stage(ls, lt, lk);
            CP_COMMIT();
            if (++lk == KI) { lk = 0; lt += GRID_CTAS; }
            if (++cs == NSTAGE) cs = 0;
        }

        const int gp = lane >> 2;
        const int tg = lane & 3;
        const int m_b = (t >> 2) * BM;
#pragma unroll
        for (int mf = 0; mf < 4; mf++) {
#pragma unroll
            for (int nf = 0; nf < 8; nf++) {
                int n  = n_base + wn + nf * 8 + tg * 2;
                int m0 = m_b + wm + mf * 16 + gp;
                float2 v0 = make_float2(acc[mf][nf][0] + bias_v[nf][0],
                                        acc[mf][nf][1] + bias_v[nf][1]);
                float2 v1 = make_float2(acc[mf][nf][2] + bias_v[nf][0],
                                        acc[mf][nf][3] + bias_v[nf][1]);
                *reinterpret_cast<float2*>(out + (size_t)m0 * O_DIM + n)       = v0;
                *reinterpret_cast<float2*>(out + (size_t)(m0 + 8) * O_DIM + n) = v1;
            }
        }
    }
}

// ---------------- launch --------------------
extern "C" void kernel_launch(void* const* d_in, const int* in_sizes, int n_in,
                              void* d_out, int out_size) {
    const float* x      = (const float*)d_in[0];
    const float* bases  = (const float*)d_in[1];
    const float* slopes = (const float*)d_in[2];
    const float* mix    = (const float*)d_in[3];
    const float* bias   = (const float*)d_in[4];
    float* out = (float*)d_out;

    cudaFuncSetAttribute(kan_gemm_kernel,
                         cudaFuncAttributeMaxDynamicSharedMemorySize, SMEM_BYTES);

    prep_kernel<<<288, 256>>>(mix, bases, slopes);
    spline_kernel<<<(B_ROWS * D_DIM / 4) / 512, 256>>>(x);   // 16384 blocks
    kan_gemm_kernel<<<GRID_CTAS, GT, SMEM_BYTES>>>(bias, out);
}

// round 16
// speedup vs baseline: 1.4507x; 1.4507x over previous
#include <cuda_runtime.h>
#include <cuda_fp16.h>
#include <cstdint>

// ---------------- problem constants ----------------
static constexpr int B_ROWS = 65536;
static constexpr int D_DIM  = 512;   // K
static constexpr int O_DIM  = 512;   // N
static constexpr int GRID_G = 16;

// ---------------- scratch (no allocs allowed) ----------------
__device__ __half g_A_h[(size_t)B_ROWS * D_DIM];
__device__ __half g_M_h[(size_t)O_DIM * D_DIM];
__device__ float2 g_tab[D_DIM * GRID_G];     // (base, slope) packed

// ---------------- kernel 0: mix->fp16 + table pack (fused) ---------------
__global__ void __launch_bounds__(256) prep_kernel(
    const float* __restrict__ mix,
    const float* __restrict__ bases,
    const float* __restrict__ slopes)
{
    if (blockIdx.x < 256) {
        size_t i4 = (size_t)blockIdx.x * 256 + threadIdx.x;   // 65536 float4s
        float4 mv = reinterpret_cast<const float4*>(mix)[i4];
        union { __half h[4]; uint2 v; } o;
        o.h[0] = __float2half_rn(mv.x);
        o.h[1] = __float2half_rn(mv.y);
        o.h[2] = __float2half_rn(mv.z);
        o.h[3] = __float2half_rn(mv.w);
        reinterpret_cast<uint2*>(g_M_h)[i4] = o.v;
    } else {
        int i = (blockIdx.x - 256) * 256 + threadIdx.x;       // 0..8191
        g_tab[i] = make_float2(bases[i], slopes[i]);
    }
}

// ---------------- kernel 1: spline -> fp16 (round-3 proven simple form) ------
__global__ void __launch_bounds__(256) spline_kernel(const float* __restrict__ x)
{
    const float NORM_MAX = 1.0f - 1e-6f;
    size_t i4 = (size_t)blockIdx.x * blockDim.x + threadIdx.x;   // one float4
    float4 xv = reinterpret_cast<const float4*>(x)[i4];
    int d0 = (int)((i4 * 4) & (D_DIM - 1));
    float xs[4] = {xv.x, xv.y, xv.z, xv.w};
    union { __half h[4]; uint2 v; } o;
#pragma unroll
    for (int j = 0; j < 4; j++) {
        // bit-exact op order vs reference: (x+1)*0.5 (== /2), clip, *16 (exact), trunc
        float xn = (xs[j] + 1.0f) * 0.5f;
        xn = fminf(fmaxf(xn, 0.0f), NORM_MAX);
        float t = xn * 16.0f;
        int idx = (int)t;
        idx = idx < 0 ? 0 : (idx > GRID_G - 1 ? GRID_G - 1 : idx);
        float xl = t - (float)idx;
        float2 bs = __ldg(&g_tab[(d0 + j) * GRID_G + idx]);
        o.h[j] = __float2half_rn(bs.x + bs.y * xl);
    }
    reinterpret_cast<uint2*>(g_A_h)[i4] = o.v;
}

// ---------------- GEMM: persistent, 4 warps, warp tile 64x64 -------
static constexpr int BM = 128;
static constexpr int BN = 128;
static constexpr int BK = 64;
static constexpr int NSTAGE = 3;
static constexpr int KI = D_DIM / BK;                    // 8 k-iters per tile
static constexpr int STAGE_BYTES = (BM + BN) * BK * 2;   // 32 KB
static constexpr int SMEM_BYTES = NSTAGE * STAGE_BYTES;  // 96 KB
static constexpr int N_TILES = (B_ROWS / BM) * (O_DIM / BN);   // 2048
static constexpr int GRID_CTAS = 296;    // exactly 2 CTA/SM x 148 SMs; mult of 4
static constexpr int GT = 128;           // GEMM threads

__device__ __forceinline__ uint32_t smem_u32(const void* p) {
    uint32_t a;
    asm("{ .reg .u64 t; cvta.to.shared.u64 t, %1; cvt.u32.u64 %0, t; }" : "=r"(a) : "l"(p));
    return a;
}
__device__ __forceinline__ void cp_async16(uint32_t dst, const void* src) {
    asm volatile("cp.async.cg.shared.global [%0], [%1], 16;" :: "r"(dst), "l"(src));
}
#define CP_COMMIT() asm volatile("cp.async.commit_group;" ::: "memory")
template<int N>
__device__ __forceinline__ void cp_wait() {
    asm volatile("cp.async.wait_group %0;" :: "n"(N) : "memory");
}
__device__ __forceinline__ void ldsm_x4(uint32_t (&r)[4], uint32_t addr) {
    asm volatile("ldmatrix.sync.aligned.m8n8.x4.shared.b16 {%0,%1,%2,%3}, [%4];"
                 : "=r"(r[0]), "=r"(r[1]), "=r"(r[2]), "=r"(r[3]) : "r"(addr));
}
__device__ __forceinline__ void mma_16816(float (&c)[4], const uint32_t (&a)[4],
                                          uint32_t b0, uint32_t b1) {
    asm volatile(
        "mma.sync.aligned.m16n8k16.row.col.f32.f16.f16.f32 "
        "{%0,%1,%2,%3}, {%4,%5,%6,%7}, {%8,%9}, {%0,%1,%2,%3};"
        : "+f"(c[0]), "+f"(c[1]), "+f"(c[2]), "+f"(c[3])
        : "r"(a[0]), "r"(a[1]), "r"(a[2]), "r"(a[3]), "r"(b0), "r"(b1));
}
__device__ __forceinline__ uint32_t tile_addr(uint32_t base, int row, int kchunk) {
    return base + row * 128 + (((uint32_t)kchunk ^ ((uint32_t)row & 7)) << 4);
}

__global__ void __launch_bounds__(GT, 2) kan_gemm_kernel(
    const float* __restrict__ bias, float* __restrict__ out)
{
    extern __shared__ uint8_t smem[];
    const int tid  = threadIdx.x;
    const int wid  = tid >> 5;
    const int lane = tid & 31;
    const int wm = (wid & 1) * 64;           // 2 warps in M
    const int wn = (wid >> 1) * 64;          // 2 warps in N

    const int cta = blockIdx.x;
    const int n_base = (cta & 3) * BN;       // fixed for this CTA

    const uint32_t smem_base = smem_u32(smem);
    uint32_t sA[NSTAGE], sB[NSTAGE];
#pragma unroll
    for (int s = 0; s < NSTAGE; s++) {
        sA[s] = smem_base + s * STAGE_BYTES;
        sB[s] = sA[s] + BM * BK * 2;
    }

    auto load_stage = [&](int stage, int lt, int lk) {
        const int m_b  = (lt >> 2) * BM;
        const int koff = lk * BK;
#pragma unroll
        for (int j = 0; j < 8; j++) {
            int ch  = tid + j * GT;          // 0..1023
            int row = ch >> 3, c = ch & 7;
            cp_async16(tile_addr(sA[stage], row, c),
                       g_A_h + (size_t)(m_b + row) * D_DIM + koff + c * 8);
        }
#pragma unroll
        for (int j = 0; j < 8; j++) {
            int ch  = tid + j * GT;
            int row = ch >> 3, c = ch & 7;
            cp_async16(tile_addr(sB[stage], row, c),
                       g_M_h + (size_t)(n_base + row) * D_DIM + koff + c * 8);
        }
    };

    float bias_v[8][2];
    {
        const int tg = lane & 3;
#pragma unroll
        for (int nf = 0; nf < 8; nf++) {
            int n = n_base + wn + nf * 8 + tg * 2;
            bias_v[nf][0] = __ldg(bias + n);
            bias_v[nf][1] = __ldg(bias + n + 1);
        }
    }

    int lt = cta, lk = 0;
    load_stage(0, lt, lk); CP_COMMIT();
    if (++lk == KI) { lk = 0; lt += GRID_CTAS; }
    load_stage(1, lt, lk); CP_COMMIT();
    if (++lk == KI) { lk = 0; lt += GRID_CTAS; }

    int cs = 0;
    for (int t = cta; t < N_TILES; t += GRID_CTAS) {
        float acc[4][8][4];
#pragma unroll
        for (int i = 0; i < 4; i++)
#pragma unroll
            for (int j = 0; j < 8; j++)
#pragma unroll
                for (int k = 0; k < 4; k++) acc[i][j][k] = 0.0f;

        for (int it = 0; it < KI; it++) {
            cp_wait<1>();
            __syncthreads();

            const uint32_t a_base = sA[cs];
            const uint32_t b_base = sB[cs];

#pragma unroll
            for (int s = 0; s < BK / 16; s++) {
                uint32_t afr[4][4];
#pragma unroll
                for (int mf = 0; mf < 4; mf++) {
                    int row = wm + mf * 16 + (lane & 15);
                    int kc  = 2 * s + (lane >> 4);
                    ldsm_x4(afr[mf], tile_addr(a_base, row, kc));
                }
                uint32_t bfr[8][2];
#pragma unroll
                for (int h = 0; h < 4; h++) {
                    int row = wn + h * 16 + (lane & 7) + ((lane >> 4) << 3);
                    int kc  = 2 * s + ((lane >> 3) & 1);
                    uint32_t r[4];
                    ldsm_x4(r, tile_addr(b_base, row, kc));
                    bfr[h * 2 + 0][0] = r[0]; bfr[h * 2 + 0][1] = r[1];
                    bfr[h * 2 + 1][0] = r[2]; bfr[h * 2 + 1][1] = r[3];
                }
#pragma unroll
                for (int mf = 0; mf < 4; mf++)
#pragma unroll
                    for (int nf = 0; nf < 8; nf++)
                        mma_16816(acc[mf][nf], afr[mf], bfr[nf][0], bfr[nf][1]);
            }

            int ls = cs + 2; if (ls >= NSTAGE) ls -= NSTAGE;
            if (lt < N_TILES) load_stage(ls, lt, lk);
            CP_COMMIT();
            if (++lk == KI) { lk = 0; lt += GRID_CTAS; }
            if (++cs == NSTAGE) cs = 0;
        }

        const int gp = lane >> 2;
        const int tg = lane & 3;
        const int m_b = (t >> 2) * BM;
#pragma unroll
        for (int mf = 0; mf < 4; mf++) {
#pragma unroll
            for (int nf = 0; nf < 8; nf++) {
                int n  = n_base + wn + nf * 8 + tg * 2;
                int m0 = m_b + wm + mf * 16 + gp;
                float2 v0 = make_float2(acc[mf][nf][0] + bias_v[nf][0],
                                        acc[mf][nf][1] + bias_v[nf][1]);
                float2 v1 = make_float2(acc[mf][nf][2] + bias_v[nf][0],
                                        acc[mf][nf][3] + bias_v[nf][1]);
                *reinterpret_cast<float2*>(out + (size_t)m0 * O_DIM + n)       = v0;
                *reinterpret_cast<float2*>(out + (size_t)(m0 + 8) * O_DIM + n) = v1;
            }
        }
    }
}

// ---------------- launch --------------------
extern "C" void kernel_launch(void* const* d_in, const int* in_sizes, int n_in,
                              void* d_out, int out_size) {
    const float* x      = (const float*)d_in[0];
    const float* bases  = (const float*)d_in[1];
    const float* slopes = (const float*)d_in[2];
    const float* mix    = (const float*)d_in[3];
    const float* bias   = (const float*)d_in[4];
    float* out = (float*)d_out;

    cudaFuncSetAttribute(kan_gemm_kernel,
                         cudaFuncAttributeMaxDynamicSharedMemorySize, SMEM_BYTES);

    prep_kernel<<<288, 256>>>(mix, bases, slopes);
    spline_kernel<<<(B_ROWS * D_DIM / 4) / 256, 256>>>(x);
    kan_gemm_kernel<<<GRID_CTAS, GT, SMEM_BYTES>>>(bias, out);
}